// round 16
// baseline (speedup 1.0000x reference)
#include <cuda_runtime.h>
#include <cuda_bf16.h>
#include <cuda_fp16.h>
#include <math.h>
#include <stdint.h>

typedef __nv_bfloat16 bf16;
typedef __half fp16;

#define BB 2
#define LL 4
#define SS 2048
#define DD 1024
#define HH 16
#define HDD 64
#define MLPD 4096
#define EPSV 1e-5f
#define BSR (BB*SS)
#define BLSR (BB*LL*SS)

// ================= scratch =================
static __device__ float g_normsum[(size_t)BSR*DD];
static __device__ float g_proj[(size_t)BSR*DD];
static __device__ float g_out1[(size_t)BSR*DD];
static __device__ float g_ffn2[(size_t)BSR*DD];

static __device__ fp16 g_lof[(size_t)BLSR*DD];         // activations, single fp16 plane
static __device__ fp16 g_cxf[(size_t)BSR*DD];          // ctx fp16
static __device__ fp16 g_o1f[(size_t)BSR*DD];          // out1 fp16
static __device__ fp16 g_f1f[(size_t)BSR*MLPD];        // gelu(ffn1) fp16
// weights: fp16 hi/lo, [N,K]
static __device__ fp16 g_wqh[(size_t)DD*DD],  g_wql[(size_t)DD*DD];
static __device__ fp16 g_wkh[(size_t)DD*DD],  g_wkl[(size_t)DD*DD];
static __device__ fp16 g_wvh[(size_t)DD*DD],  g_wvl[(size_t)DD*DD];
static __device__ fp16 g_woh[(size_t)DD*DD],  g_wol[(size_t)DD*DD];
static __device__ fp16 g_w1h[(size_t)MLPD*DD], g_w1l[(size_t)MLPD*DD];
static __device__ fp16 g_w2h[(size_t)DD*MLPD], g_w2l[(size_t)DD*MLPD];
// attention operands stay bf16 hi/lo [B,H,S,HD]
static __device__ bf16 g_qph[(size_t)BSR*DD], g_qpl[(size_t)BSR*DD];
static __device__ bf16 g_kph[(size_t)BSR*DD], g_kpl[(size_t)BSR*DD];
static __device__ bf16 g_vph[(size_t)BSR*DD], g_vpl[(size_t)BSR*DD];

// ================= PTX helpers =================
__device__ __forceinline__ uint32_t smem_u32(const void* p) {
    uint32_t a;
    asm("{ .reg .u64 t; cvta.to.shared.u64 t, %1; cvt.u32.u64 %0, t; }" : "=r"(a) : "l"(p));
    return a;
}
__device__ __forceinline__ void cpasync16(uint32_t dst, const void* src) {
    asm volatile("cp.async.cg.shared.global [%0], [%1], 16;" :: "r"(dst), "l"(src));
}
#define CP_COMMIT() asm volatile("cp.async.commit_group;" ::: "memory")
#define CP_WAIT0()  asm volatile("cp.async.wait_group 0;" ::: "memory")
#define CP_WAIT1()  asm volatile("cp.async.wait_group 1;" ::: "memory")
#define CP_WAIT2()  asm volatile("cp.async.wait_group 2;" ::: "memory")

__device__ __forceinline__ void ldsm4(uint32_t* r, uint32_t addr) {
    asm volatile("ldmatrix.sync.aligned.m8n8.x4.shared.b16 {%0,%1,%2,%3}, [%4];"
        : "=r"(r[0]), "=r"(r[1]), "=r"(r[2]), "=r"(r[3]) : "r"(addr));
}
__device__ __forceinline__ void ldsm4t(uint32_t* r, uint32_t addr) {
    asm volatile("ldmatrix.sync.aligned.m8n8.x4.trans.shared.b16 {%0,%1,%2,%3}, [%4];"
        : "=r"(r[0]), "=r"(r[1]), "=r"(r[2]), "=r"(r[3]) : "r"(addr));
}
// bf16 mma (attention)
__device__ __forceinline__ void mma16816(float* d, const uint32_t* a, const uint32_t* b) {
    asm volatile("mma.sync.aligned.m16n8k16.row.col.f32.bf16.bf16.f32 "
        "{%0,%1,%2,%3}, {%4,%5,%6,%7}, {%8,%9}, {%0,%1,%2,%3};"
        : "+f"(d[0]), "+f"(d[1]), "+f"(d[2]), "+f"(d[3])
        : "r"(a[0]), "r"(a[1]), "r"(a[2]), "r"(a[3]), "r"(b[0]), "r"(b[1]));
}
// fp16 mma (linear GEMMs)
__device__ __forceinline__ void mma16816h(float* d, const uint32_t* a, const uint32_t* b) {
    asm volatile("mma.sync.aligned.m16n8k16.row.col.f32.f16.f16.f32 "
        "{%0,%1,%2,%3}, {%4,%5,%6,%7}, {%8,%9}, {%0,%1,%2,%3};"
        : "+f"(d[0]), "+f"(d[1]), "+f"(d[2]), "+f"(d[3])
        : "r"(a[0]), "r"(a[1]), "r"(a[2]), "r"(a[3]), "r"(b[0]), "r"(b[1]));
}
__device__ __forceinline__ void split1(float v, bf16& h, bf16& l) {
    h = __float2bfloat16_rn(v);
    l = __float2bfloat16_rn(v - __bfloat162float(h));
}
__device__ __forceinline__ void split2u(float a, float b, uint32_t& hi, uint32_t& lo) {
    bf16 ha, la, hb, lb;
    split1(a, ha, la); split1(b, hb, lb);
    __nv_bfloat162 H(ha, hb), L(la, lb);
    hi = *(uint32_t*)&H; lo = *(uint32_t*)&L;
}
__device__ __forceinline__ void hsplit1(float v, fp16& h, fp16& l) {
    h = __float2half_rn(v);
    l = __float2half_rn(v - __half2float(h));
}

// ================= fp16 GEMM 128x128 (proj/FFN), K chunk 32, 3-stage =================
#define PL_A  0
#define PL_BH 8192
#define PL_BL 16384
#define STAGE_B 24576
#define GEMM_SMEM (3*24576)

__device__ __forceinline__ void load_stage(uint32_t st,
        const fp16* __restrict__ A,
        const fp16* __restrict__ Bh, const fp16* __restrict__ Bl,
        int K, int kt, int tid) {
    const fp16* gsrc[3] = { A, Bh, Bl };
#pragma unroll
    for (int p = 0; p < 3; p++) {
        const fp16* g = gsrc[p] + kt * 32;
#pragma unroll
        for (int i = tid; i < 512; i += 256) {
            int r = i >> 2, c = i & 3;
            uint32_t d = st + p * 8192 + r * 64 + (((c ^ ((r >> 1) & 3))) << 4);
            cpasync16(d, g + (size_t)r * K + c * 8);
        }
    }
    CP_COMMIT();
}

__device__ __forceinline__ void gemm_core(uint32_t sb, float acc[4][4][4],
        const fp16* A, const fp16* Bh, const fp16* Bl,
        int K, int tid, const uint32_t* aRowOff, const uint32_t* aSwz,
        const uint32_t* bRowOff, const uint32_t* bSwz, int lchunk) {
    const int nch = K / 32;
    load_stage(sb, A, Bh, Bl, K, 0, tid);
    if (nch > 1) load_stage(sb + STAGE_B, A, Bh, Bl, K, 1, tid);
    for (int kt = 0; kt < nch; kt++) {
        int buf = kt % 3;
        if (kt + 2 < nch) {
            load_stage(sb + ((kt + 2) % 3) * STAGE_B, A, Bh, Bl, K, kt + 2, tid);
            CP_WAIT2();
        } else if (kt + 1 < nch) {
            CP_WAIT1();
        } else {
            CP_WAIT0();
        }
        __syncthreads();
        uint32_t st = sb + buf * STAGE_B;
#pragma unroll
        for (int s = 0; s < 2; s++) {
            uint32_t ch = (uint32_t)(s * 2 + lchunk);
            uint32_t aF[4][4], bHf[4][2], bLf[4][2];
#pragma unroll
            for (int mt = 0; mt < 4; mt++)
                ldsm4(aF[mt], st + PL_A + aRowOff[mt] + ((ch ^ aSwz[mt]) << 4));
#pragma unroll
            for (int p = 0; p < 2; p++) {
                uint32_t t[4];
                ldsm4(t, st + PL_BH + bRowOff[p] + ((ch ^ bSwz[p]) << 4));
                bHf[2*p][0] = t[0]; bHf[2*p][1] = t[2];
                bHf[2*p+1][0] = t[1]; bHf[2*p+1][1] = t[3];
                ldsm4(t, st + PL_BL + bRowOff[p] + ((ch ^ bSwz[p]) << 4));
                bLf[2*p][0] = t[0]; bLf[2*p][1] = t[2];
                bLf[2*p+1][0] = t[1]; bLf[2*p+1][1] = t[3];
            }
#pragma unroll
            for (int mt = 0; mt < 4; mt++)
#pragma unroll
                for (int nt = 0; nt < 4; nt++) mma16816h(acc[mt][nt], aF[mt], bHf[nt]);
#pragma unroll
            for (int mt = 0; mt < 4; mt++)
#pragma unroll
                for (int nt = 0; nt < 4; nt++) mma16816h(acc[mt][nt], aF[mt], bLf[nt]);
        }
        __syncthreads();
    }
}

struct GArgs {
    const fp16 *A, *Bh, *Bl;
    float* C;
    const float* bias;
    fp16* Cf;
    int N, K;
};

// EPI 0: fp32 C.  EPI 1: gelu(acc+bias) -> fp16 plane.
template<int EPI>
__global__ __launch_bounds__(256, 2) void gemm_mma(const GArgs args) {
    extern __shared__ char smem[];
    uint32_t sb = smem_u32(smem);
    int tid = threadIdx.x, lane = tid & 31, wid = tid >> 5;
    int wm = wid >> 2, wn = wid & 3;
    const int K = args.K, N = args.N;
    const fp16* A  = args.A  + (size_t)(blockIdx.y * 128) * K;
    const fp16* Bh = args.Bh + (size_t)(blockIdx.x * 128) * K;
    const fp16* Bl = args.Bl + (size_t)(blockIdx.x * 128) * K;

    float acc[4][4][4];
#pragma unroll
    for (int i = 0; i < 4; i++)
#pragma unroll
        for (int j = 0; j < 4; j++)
#pragma unroll
            for (int c = 0; c < 4; c++) acc[i][j][c] = 0.f;

    int lrow = lane & 15, lchunk = lane >> 4;
    uint32_t aRowOff[4], aSwz[4], bRowOff[2], bSwz[2];
#pragma unroll
    for (int mt = 0; mt < 4; mt++) {
        int r = wm * 64 + mt * 16 + lrow;
        aRowOff[mt] = r * 64; aSwz[mt] = (r >> 1) & 3;
    }
#pragma unroll
    for (int p = 0; p < 2; p++) {
        int r = wn * 32 + p * 16 + lrow;
        bRowOff[p] = r * 64; bSwz[p] = (r >> 1) & 3;
    }

    gemm_core(sb, acc, A, Bh, Bl, K, tid, aRowOff, aSwz, bRowOff, bSwz, lchunk);

    int g = lane >> 2, tc = lane & 3;
#pragma unroll
    for (int mt = 0; mt < 4; mt++) {
        int row = blockIdx.y * 128 + wm * 64 + mt * 16 + g;
#pragma unroll
        for (int nt = 0; nt < 4; nt++) {
            int col = blockIdx.x * 128 + wn * 32 + nt * 8 + tc * 2;
            if (EPI == 0) {
                *(float2*)&args.C[(size_t)row * N + col]       = make_float2(acc[mt][nt][0], acc[mt][nt][1]);
                *(float2*)&args.C[(size_t)(row + 8) * N + col] = make_float2(acc[mt][nt][2], acc[mt][nt][3]);
            } else {
                float b0 = args.bias[col], b1 = args.bias[col + 1];
                float v0 = acc[mt][nt][0] + b0, v1 = acc[mt][nt][1] + b1;
                float v2 = acc[mt][nt][2] + b0, v3 = acc[mt][nt][3] + b1;
                v0 *= normcdff(v0); v1 *= normcdff(v1); v2 *= normcdff(v2); v3 *= normcdff(v3);
                *(__half2*)&args.Cf[(size_t)row * N + col]       = __floats2half2_rn(v0, v1);
                *(__half2*)&args.Cf[(size_t)(row + 8) * N + col] = __floats2half2_rn(v2, v3);
            }
        }
    }
}

// ================= fused QKV GEMM + GRN epilogue (128M x 64N tile) =================
#define QPL_A  0
#define QPL_BH 8192
#define QPL_BL 12288
#define QSTAGE_B 16384
#define QKV_SMEM (3*16384)

__device__ __forceinline__ void load_stage_q(uint32_t st,
        const fp16* __restrict__ A,
        const fp16* __restrict__ Bh, const fp16* __restrict__ Bl,
        int kt, int tid) {
    const fp16* gA = A + kt * 32;
#pragma unroll
    for (int i = tid; i < 512; i += 256) {
        int r = i >> 2, c = i & 3;
        uint32_t d = st + QPL_A + r * 64 + (((c ^ ((r >> 1) & 3))) << 4);
        cpasync16(d, gA + (size_t)r * DD + c * 8);
    }
    {
        int i = tid;             // 256 chunks per B plane, one per thread
        int r = i >> 2, c = i & 3;
        uint32_t off = r * 64 + (((c ^ ((r >> 1) & 3))) << 4);
        cpasync16(st + QPL_BH + off, Bh + kt * 32 + (size_t)r * DD + c * 8);
        cpasync16(st + QPL_BL + off, Bl + kt * 32 + (size_t)r * DD + c * 8);
    }
    CP_COMMIT();
}

__device__ __forceinline__ void gemm_core_q(uint32_t sb, float acc[2][4][4],
        const fp16* A, const fp16* Bh, const fp16* Bl,
        int tid, const uint32_t* aRowOff, const uint32_t* aSwz,
        const uint32_t* bRowOff, const uint32_t* bSwz, int lchunk) {
    const int nch = DD / 32;
    load_stage_q(sb, A, Bh, Bl, 0, tid);
    load_stage_q(sb + QSTAGE_B, A, Bh, Bl, 1, tid);
    for (int kt = 0; kt < nch; kt++) {
        int buf = kt % 3;
        if (kt + 2 < nch) {
            load_stage_q(sb + ((kt + 2) % 3) * QSTAGE_B, A, Bh, Bl, kt + 2, tid);
            CP_WAIT2();
        } else if (kt + 1 < nch) {
            CP_WAIT1();
        } else {
            CP_WAIT0();
        }
        __syncthreads();
        uint32_t st = sb + buf * QSTAGE_B;
#pragma unroll
        for (int s = 0; s < 2; s++) {
            uint32_t ch = (uint32_t)(s * 2 + lchunk);
            uint32_t aF[2][4], bHf[4][2], bLf[4][2];
#pragma unroll
            for (int mt = 0; mt < 2; mt++)
                ldsm4(aF[mt], st + QPL_A + aRowOff[mt] + ((ch ^ aSwz[mt]) << 4));
#pragma unroll
            for (int p = 0; p < 2; p++) {
                uint32_t t[4];
                ldsm4(t, st + QPL_BH + bRowOff[p] + ((ch ^ bSwz[p]) << 4));
                bHf[2*p][0] = t[0]; bHf[2*p][1] = t[2];
                bHf[2*p+1][0] = t[1]; bHf[2*p+1][1] = t[3];
                ldsm4(t, st + QPL_BL + bRowOff[p] + ((ch ^ bSwz[p]) << 4));
                bLf[2*p][0] = t[0]; bLf[2*p][1] = t[2];
                bLf[2*p+1][0] = t[1]; bLf[2*p+1][1] = t[3];
            }
#pragma unroll
            for (int mt = 0; mt < 2; mt++)
#pragma unroll
                for (int nt = 0; nt < 4; nt++) mma16816h(acc[mt][nt], aF[mt], bHf[nt]);
#pragma unroll
            for (int mt = 0; mt < 2; mt++)
#pragma unroll
                for (int nt = 0; nt < 4; nt++) mma16816h(acc[mt][nt], aF[mt], bLf[nt]);
        }
        __syncthreads();
    }
}

struct QkvArgs {
    const fp16* A;                        // [BLSR, DD]
    const fp16 *Bh[3], *Bl[3];
    const float *bias[3], *gain[3], *beta[3];
    bf16 *Oh[3], *Ol[3];
};

__global__ __launch_bounds__(256, 2) void gemm_qkv(const QkvArgs args) {
    extern __shared__ char smem[];
    uint32_t sb = smem_u32(smem);
    int tid = threadIdx.x, lane = tid & 31, wid = tid >> 5;
    int wm = wid >> 1, wn = wid & 1;      // 4x2 warps; warp tile 32m x 32n
    int z = blockIdx.z;
    int bx = blockIdx.x;                  // 64-col N tile == head index
    int by = blockIdx.y;
    int b = (by * 128) / SS;
    int s0 = by * 128 - b * SS;
    const fp16* Bh = args.Bh[z] + (size_t)(bx * 64) * DD;
    const fp16* Bl = args.Bl[z] + (size_t)(bx * 64) * DD;

    int lrow = lane & 15, lchunk = lane >> 4;
    uint32_t aRowOff[2], aSwz[2], bRowOff[2], bSwz[2];
#pragma unroll
    for (int mt = 0; mt < 2; mt++) {
        int r = wm * 32 + mt * 16 + lrow;
        aRowOff[mt] = r * 64; aSwz[mt] = (r >> 1) & 3;
    }
#pragma unroll
    for (int p = 0; p < 2; p++) {
        int r = wn * 32 + p * 16 + lrow;
        bRowOff[p] = r * 64; bSwz[p] = (r >> 1) & 3;
    }
    int g = lane >> 2, tc = lane & 3;

    float bs0[4], bs1[4];
#pragma unroll
    for (int nt = 0; nt < 4; nt++) {
        int col = bx * 64 + wn * 32 + nt * 8 + tc * 2;
        bs0[nt] = args.bias[z][col];
        bs1[nt] = args.bias[z][col + 1];
    }

    float sum[2][4][4];
#pragma unroll
    for (int i = 0; i < 2; i++)
#pragma unroll
        for (int j = 0; j < 4; j++)
#pragma unroll
            for (int c = 0; c < 4; c++) sum[i][j][c] = 0.f;

    for (int l = 0; l < LL; l++) {
        const fp16* A = args.A + ((size_t)((b * LL + l) * SS + s0)) * DD;
        float acc[2][4][4];
#pragma unroll
        for (int i = 0; i < 2; i++)
#pragma unroll
            for (int j = 0; j < 4; j++)
#pragma unroll
                for (int c = 0; c < 4; c++) acc[i][j][c] = 0.f;

        gemm_core_q(sb, acc, A, Bh, Bl, tid, aRowOff, aSwz, bRowOff, bSwz, lchunk);

#pragma unroll
        for (int mt = 0; mt < 2; mt++)
#pragma unroll
            for (int nt = 0; nt < 4; nt++) {
                sum[mt][nt][0] += fmaxf(acc[mt][nt][0] + bs0[nt], 0.f);
                sum[mt][nt][1] += fmaxf(acc[mt][nt][1] + bs1[nt], 0.f);
                sum[mt][nt][2] += fmaxf(acc[mt][nt][2] + bs0[nt], 0.f);
                sum[mt][nt][3] += fmaxf(acc[mt][nt][3] + bs1[nt], 0.f);
            }
    }

    // epilogue: + g*normsum + L*be -> bf16 hi/lo head layout; head h == bx
#pragma unroll
    for (int nt = 0; nt < 4; nt++) {
        int inner = wn * 32 + nt * 8 + tc * 2;     // hd within head
        int col = bx * 64 + inner;
        float gg0 = args.gain[z][col], gg1 = args.gain[z][col + 1];
        float be0 = args.beta[z][col], be1 = args.beta[z][col + 1];
#pragma unroll
        for (int mt = 0; mt < 2; mt++) {
            int rl = wm * 32 + mt * 16 + g;
            int nsrow = by * 128 + rl;
            int s = s0 + rl;
            float2 ns0 = *(const float2*)&g_normsum[(size_t)nsrow * DD + col];
            float2 ns1 = *(const float2*)&g_normsum[(size_t)(nsrow + 8) * DD + col];
            float v0 = sum[mt][nt][0] + gg0 * ns0.x + LL * be0;
            float v1 = sum[mt][nt][1] + gg1 * ns0.y + LL * be1;
            float v2 = sum[mt][nt][2] + gg0 * ns1.x + LL * be0;
            float v3 = sum[mt][nt][3] + gg1 * ns1.y + LL * be1;
            uint32_t h01, l01, h23, l23;
            split2u(v0, v1, h01, l01);
            split2u(v2, v3, h23, l23);
            size_t o0 = ((size_t)(b * HH + bx) * SS + s) * HDD + inner;
            size_t o1 = ((size_t)(b * HH + bx) * SS + s + 8) * HDD + inner;
            *(uint32_t*)&args.Oh[z][o0] = h01;
            *(uint32_t*)&args.Ol[z][o0] = l01;
            *(uint32_t*)&args.Oh[z][o1] = h23;
            *(uint32_t*)&args.Ol[z][o1] = l23;
        }
    }
}

// ================= tensor-core flash attention (bf16 x3, unchanged math) =================
#define AT_STAGE 32768
#define AT_SMEM  65536

__device__ __forceinline__ void attn_load_kv(uint32_t st, int bh, int kt, int tid) {
    const bf16* src[4] = {
        g_kph + ((size_t)bh * SS + kt * 64) * HDD,
        g_kpl + ((size_t)bh * SS + kt * 64) * HDD,
        g_vph + ((size_t)bh * SS + kt * 64) * HDD,
        g_vpl + ((size_t)bh * SS + kt * 64) * HDD };
#pragma unroll
    for (int p = 0; p < 4; p++) {
#pragma unroll
        for (int i = tid; i < 512; i += 128) {
            int r = i >> 3, c = i & 7;
            uint32_t d = st + p * 8192 + r * 128 + (((c ^ (r & 7))) << 4);
            cpasync16(d, src[p] + (size_t)r * HDD + c * 8);
        }
    }
    CP_COMMIT();
}

__global__ __launch_bounds__(128, 3) void attn_mma() {
    extern __shared__ char smem[];
    uint32_t sb = smem_u32(smem);
    int tid = threadIdx.x, lane = tid & 31, wid = tid >> 5;
    int qt = blockIdx.x, bh = blockIdx.y;
    int b = bh / HH, h = bh % HH;
    int g = lane >> 2, tc = lane & 3;
    int lrow = lane & 15, lchunk = lane >> 4;

    {
        const bf16* qsrc[2] = {
            g_qph + ((size_t)bh * SS + qt * 64) * HDD,
            g_qpl + ((size_t)bh * SS + qt * 64) * HDD };
#pragma unroll
        for (int p = 0; p < 2; p++)
#pragma unroll
            for (int i = tid; i < 512; i += 128) {
                int r = i >> 3, c = i & 7;
                uint32_t d = sb + p * 8192 + r * 128 + (((c ^ (r & 7))) << 4);
                cpasync16(d, qsrc[p] + (size_t)r * HDD + c * 8);
            }
        CP_COMMIT(); CP_WAIT0();
        __syncthreads();
    }
    uint32_t qhF[4][4], qlF[4][4];
#pragma unroll
    for (int ks = 0; ks < 4; ks++) {
        int r = wid * 16 + lrow;
        uint32_t cc = (uint32_t)(ks * 2 + lchunk);
        uint32_t off = r * 128 + ((cc ^ (r & 7)) << 4);
        ldsm4(qhF[ks], sb + off);
        ldsm4(qlF[ks], sb + 8192 + off);
    }
    __syncthreads();

    float o[8][4];
#pragma unroll
    for (int i = 0; i < 8; i++)
#pragma unroll
        for (int c = 0; c < 4; c++) o[i][c] = 0.f;
    float m0 = -INFINITY, m1 = -INFINITY, l0 = 0.f, l1 = 0.f;
    const float ls = 0.125f * 1.44269504088896f;

    attn_load_kv(sb, bh, 0, tid);

    for (int kt = 0; kt < SS / 64; kt++) {
        int buf = kt & 1;
        if (kt + 1 < SS / 64) {
            attn_load_kv(sb + (buf ^ 1) * AT_STAGE, bh, kt + 1, tid);
            CP_WAIT1();
        } else {
            CP_WAIT0();
        }
        __syncthreads();
        uint32_t st = sb + buf * AT_STAGE;

        float S[8][4];
#pragma unroll
        for (int i = 0; i < 8; i++)
#pragma unroll
            for (int c = 0; c < 4; c++) S[i][c] = 0.f;
#pragma unroll
        for (int np = 0; np < 4; np++) {
            int r = np * 16 + lrow;
#pragma unroll
            for (int ks = 0; ks < 4; ks++) {
                uint32_t cc = (uint32_t)(ks * 2 + lchunk);
                uint32_t off = r * 128 + ((cc ^ (r & 7)) << 4);
                uint32_t tH[4], tL[4];
                ldsm4(tH, st + off);
                ldsm4(tL, st + 8192 + off);
                uint32_t b0h[2] = { tH[0], tH[2] }, b1h[2] = { tH[1], tH[3] };
                uint32_t b0l[2] = { tL[0], tL[2] }, b1l[2] = { tL[1], tL[3] };
                mma16816(S[2*np],   qhF[ks], b0h);
                mma16816(S[2*np+1], qhF[ks], b1h);
                mma16816(S[2*np],   qhF[ks], b0l);
                mma16816(S[2*np+1], qhF[ks], b1l);
                mma16816(S[2*np],   qlF[ks], b0h);
                mma16816(S[2*np+1], qlF[ks], b1h);
            }
        }

        float tm0 = -INFINITY, tm1 = -INFINITY;
#pragma unroll
        for (int i = 0; i < 8; i++) {
            S[i][0] *= ls; S[i][1] *= ls; S[i][2] *= ls; S[i][3] *= ls;
            tm0 = fmaxf(tm0, fmaxf(S[i][0], S[i][1]));
            tm1 = fmaxf(tm1, fmaxf(S[i][2], S[i][3]));
        }
        tm0 = fmaxf(tm0, __shfl_xor_sync(0xffffffffu, tm0, 1));
        tm0 = fmaxf(tm0, __shfl_xor_sync(0xffffffffu, tm0, 2));
        tm1 = fmaxf(tm1, __shfl_xor_sync(0xffffffffu, tm1, 1));
        tm1 = fmaxf(tm1, __shfl_xor_sync(0xffffffffu, tm1, 2));
        float nm0 = fmaxf(m0, tm0), nm1 = fmaxf(m1, tm1);
        float c0 = exp2f(m0 - nm0), c1 = exp2f(m1 - nm1);
        float ps0 = 0.f, ps1 = 0.f;
#pragma unroll
        for (int i = 0; i < 8; i++) {
            S[i][0] = exp2f(S[i][0] - nm0); S[i][1] = exp2f(S[i][1] - nm0);
            S[i][2] = exp2f(S[i][2] - nm1); S[i][3] = exp2f(S[i][3] - nm1);
            ps0 += S[i][0] + S[i][1];
            ps1 += S[i][2] + S[i][3];
        }
        ps0 += __shfl_xor_sync(0xffffffffu, ps0, 1);
        ps0 += __shfl_xor_sync(0xffffffffu, ps0, 2);
        ps1 += __shfl_xor_sync(0xffffffffu, ps1, 1);
        ps1 += __shfl_xor_sync(0xffffffffu, ps1, 2);
        l0 = l0 * c0 + ps0; l1 = l1 * c1 + ps1;
        m0 = nm0; m1 = nm1;
#pragma unroll
        for (int i = 0; i < 8; i++) {
            o[i][0] *= c0; o[i][1] *= c0; o[i][2] *= c1; o[i][3] *= c1;
        }

        uint32_t pH[4][4], pL[4][4];
#pragma unroll
        for (int j = 0; j < 4; j++) {
            split2u(S[2*j][0],   S[2*j][1],   pH[j][0], pL[j][0]);
            split2u(S[2*j][2],   S[2*j][3],   pH[j][1], pL[j][1]);
            split2u(S[2*j+1][0], S[2*j+1][1], pH[j][2], pL[j][2]);
            split2u(S[2*j+1][2], S[2*j+1][3], pH[j][3], pL[j][3]);
        }

#pragma unroll
        for (int j = 0; j < 4; j++) {
            int r = j * 16 + lrow;
#pragma unroll
            for (int dp = 0; dp < 4; dp++) {
                uint32_t cc = (uint32_t)(dp * 2 + lchunk);
                uint32_t off = r * 128 + ((cc ^ (r & 7)) << 4);
                uint32_t tH[4], tL[4];
                ldsm4t(tH, st + 16384 + off);
                ldsm4t(tL, st + 24576 + off);
                uint32_t b0h[2] = { tH[0], tH[1] }, b1h[2] = { tH[2], tH[3] };
                uint32_t b0l[2] = { tL[0], tL[1] }, b1l[2] = { tL[2], tL[3] };
                mma16816(o[2*dp],   pH[j], b0h);
                mma16816(o[2*dp+1], pH[j], b1h);
                mma16816(o[2*dp],   pH[j], b0l);
                mma16816(o[2*dp+1], pH[j], b1l);
                mma16816(o[2*dp],   pL[j], b0h);
                mma16816(o[2*dp+1], pL[j], b1h);
            }
        }
        __syncthreads();
    }

    float il0 = 1.f / l0, il1 = 1.f / l1;
    int srow = qt * 64 + wid * 16 + g;
#pragma unroll
    for (int nt = 0; nt < 8; nt++) {
        int col = h * HDD + nt * 8 + tc * 2;
        float v0 = o[nt][0] * il0, v1 = o[nt][1] * il0;
        float v2 = o[nt][2] * il1, v3 = o[nt][3] * il1;
        size_t r0 = (size_t)(b * SS + srow) * DD + col;
        size_t r1 = (size_t)(b * SS + srow + 8) * DD + col;
        *(__half2*)&g_cxf[r0] = __floats2half2_rn(v0, v1);
        *(__half2*)&g_cxf[r1] = __floats2half2_rn(v2, v3);
    }
}

// ================= fused split + normsum =================
__device__ __forceinline__ float2 blockReduce2(float s1, float s2, float* sh) {
    const unsigned FULL = 0xffffffffu;
#pragma unroll
    for (int o = 16; o; o >>= 1) {
        s1 += __shfl_xor_sync(FULL, s1, o);
        s2 += __shfl_xor_sync(FULL, s2, o);
    }
    int lane = threadIdx.x & 31, w = threadIdx.x >> 5;
    if (lane == 0) { sh[w] = s1; sh[8 + w] = s2; }
    __syncthreads();
    float t1 = 0.f, t2 = 0.f;
#pragma unroll
    for (int i = 0; i < 8; i++) { t1 += sh[i]; t2 += sh[8 + i]; }
    __syncthreads();
    return make_float2(t1, t2);
}

__global__ __launch_bounds__(256) void split_normsum_kernel(const float* __restrict__ lo,
                                                            fp16* __restrict__ of) {
    __shared__ float sh[16];
    int row = blockIdx.x;
    int b = row / SS, s = row % SS;
    int t = threadIdx.x;
    float4 acc = make_float4(0.f, 0.f, 0.f, 0.f);
    for (int l = 0; l < LL; l++) {
        size_t ridx = ((size_t)((b*LL + l)*SS + s))*DD;
        float4 v = ((const float4*)(lo + ridx))[t];
        ((__half2*)(of + ridx))[2*t]     = __floats2half2_rn(v.x, v.y);
        ((__half2*)(of + ridx))[2*t + 1] = __floats2half2_rn(v.z, v.w);
        float s1 = v.x + v.y + v.z + v.w;
        float s2 = v.x*v.x + v.y*v.y + v.z*v.z + v.w*v.w;
        float2 tot = blockReduce2(s1, s2, sh);
        float mu = tot.x * (1.f/DD);
        float var = tot.y * (1.f/DD) - mu*mu;
        float r = rsqrtf(var + EPSV);
        acc.x += (v.x - mu)*r; acc.y += (v.y - mu)*r;
        acc.z += (v.z - mu)*r; acc.w += (v.w - mu)*r;
    }
    ((float4*)(g_normsum + (size_t)row*DD))[t] = acc;
}

// ================= weight prep: W [K,N] fp32 -> [N,K] fp16 hi/lo =================
__global__ __launch_bounds__(256) void wsplit_kernel(const float* __restrict__ W,
                                                     fp16* __restrict__ oh, fp16* __restrict__ ol,
                                                     int K, int N) {
    __shared__ float tile[32][33];
    int n0 = blockIdx.x * 32, k0 = blockIdx.y * 32;
    int tx = threadIdx.x & 31, ty = threadIdx.x >> 5;
#pragma unroll
    for (int i = 0; i < 4; i++)
        tile[ty + 8 * i][tx] = W[(size_t)(k0 + ty + 8 * i) * N + n0 + tx];
    __syncthreads();
#pragma unroll
    for (int i = 0; i < 4; i++) {
        float v = tile[tx][ty + 8 * i];
        fp16 hh, ll; hsplit1(v, hh, ll);
        size_t o = (size_t)(n0 + ty + 8 * i) * K + k0 + tx;
        oh[o] = hh; ol[o] = ll;
    }
}

template<int SPLIT>
__global__ __launch_bounds__(256) void ln_residual_kernel(
        const float* __restrict__ resid, const float* __restrict__ pre,
        const float* __restrict__ bias, const float* __restrict__ gam,
        const float* __restrict__ bet, float* __restrict__ out,
        fp16* __restrict__ of) {
    __shared__ float sh[16];
    int row = blockIdx.x, t = threadIdx.x;
    float4 p = ((const float4*)(pre + (size_t)row*DD))[t];
    float4 bb = ((const float4*)bias)[t];
    p.x += bb.x; p.y += bb.y; p.z += bb.z; p.w += bb.w;
    float s1 = p.x + p.y + p.z + p.w;
    float s2 = p.x*p.x + p.y*p.y + p.z*p.z + p.w*p.w;
    float2 tot = blockReduce2(s1, s2, sh);
    float mu = tot.x * (1.f/DD);
    float var = tot.y * (1.f/DD) - mu*mu;
    float r = rsqrtf(var + EPSV);
    float4 gg = ((const float4*)gam)[t];
    float4 ee = ((const float4*)bet)[t];
    float4 rr = ((const float4*)(resid + (size_t)row*DD))[t];
    float4 o;
    o.x = rr.x + (p.x - mu)*r*gg.x + ee.x;
    o.y = rr.y + (p.y - mu)*r*gg.y + ee.y;
    o.z = rr.z + (p.z - mu)*r*gg.z + ee.z;
    o.w = rr.w + (p.w - mu)*r*gg.w + ee.w;
    ((float4*)(out + (size_t)row*DD))[t] = o;
    if (SPLIT) {
        size_t i = (size_t)row * (DD/4) + t;
        ((__half2*)of)[2 * i]     = __floats2half2_rn(o.x, o.y);
        ((__half2*)of)[2 * i + 1] = __floats2half2_rn(o.z, o.w);
    }
}

// ================= host =================
static void* symaddr(const void* sym) { void* p; cudaGetSymbolAddress(&p, sym); return p; }

extern "C" void kernel_launch(void* const* d_in, const int* in_sizes, int n_in,
                              void* d_out, int out_size) {
    const float* x   = (const float*)d_in[0];
    const float* lo  = (const float*)d_in[1];
    const float* qW  = (const float*)d_in[2];
    const float* qb  = (const float*)d_in[3];
    const float* qg  = (const float*)d_in[4];
    const float* qbe = (const float*)d_in[5];
    const float* kW  = (const float*)d_in[6];
    const float* kb  = (const float*)d_in[7];
    const float* kg  = (const float*)d_in[8];
    const float* kbe = (const float*)d_in[9];
    const float* vW  = (const float*)d_in[10];
    const float* vb  = (const float*)d_in[11];
    const float* vg  = (const float*)d_in[12];
    const float* vbe = (const float*)d_in[13];
    const float* oW  = (const float*)d_in[14];
    const float* ob  = (const float*)d_in[15];
    const float* ang = (const float*)d_in[16];
    const float* anb = (const float*)d_in[17];
    const float* W1  = (const float*)d_in[18];
    const float* b1  = (const float*)d_in[19];
    const float* W2  = (const float*)d_in[20];
    const float* b2  = (const float*)d_in[21];
    const float* fng = (const float*)d_in[22];
    const float* fnb = (const float*)d_in[23];
    float* out = (float*)d_out;

    float* proj = (float*)symaddr(g_proj);
    float* out1 = (float*)symaddr(g_out1);
    float* ffn2 = (float*)symaddr(g_ffn2);
    fp16* lof = (fp16*)symaddr(g_lof);
    fp16* cxf = (fp16*)symaddr(g_cxf);
    fp16* o1f = (fp16*)symaddr(g_o1f);
    fp16* f1f = (fp16*)symaddr(g_f1f);
    fp16 *wqh = (fp16*)symaddr(g_wqh), *wql = (fp16*)symaddr(g_wql);
    fp16 *wkh = (fp16*)symaddr(g_wkh), *wkl = (fp16*)symaddr(g_wkl);
    fp16 *wvh = (fp16*)symaddr(g_wvh), *wvl = (fp16*)symaddr(g_wvl);
    fp16 *woh = (fp16*)symaddr(g_woh), *wol = (fp16*)symaddr(g_wol);
    fp16 *w1h = (fp16*)symaddr(g_w1h), *w1l = (fp16*)symaddr(g_w1l);
    fp16 *w2h = (fp16*)symaddr(g_w2h), *w2l = (fp16*)symaddr(g_w2l);

    cudaFuncSetAttribute(gemm_mma<0>, cudaFuncAttributeMaxDynamicSharedMemorySize, GEMM_SMEM);
    cudaFuncSetAttribute(gemm_mma<1>, cudaFuncAttributeMaxDynamicSharedMemorySize, GEMM_SMEM);
    cudaFuncSetAttribute(gemm_qkv,    cudaFuncAttributeMaxDynamicSharedMemorySize, QKV_SMEM);
    cudaFuncSetAttribute(attn_mma,    cudaFuncAttributeMaxDynamicSharedMemorySize, AT_SMEM);

    // weight prep
    wsplit_kernel<<<dim3(DD/32, DD/32), 256>>>(qW, wqh, wql, DD, DD);
    wsplit_kernel<<<dim3(DD/32, DD/32), 256>>>(kW, wkh, wkl, DD, DD);
    wsplit_kernel<<<dim3(DD/32, DD/32), 256>>>(vW, wvh, wvl, DD, DD);
    wsplit_kernel<<<dim3(DD/32, DD/32), 256>>>(oW, woh, wol, DD, DD);
    wsplit_kernel<<<dim3(MLPD/32, DD/32), 256>>>(W1, w1h, w1l, DD, MLPD);
    wsplit_kernel<<<dim3(DD/32, MLPD/32), 256>>>(W2, w2h, w2l, MLPD, DD);

    // fused activation fp16 convert + norm-core sum
    split_normsum_kernel<<<BSR, 256>>>(lo, lof);

    // fused QKV GEMM + GRN epilogue -> q/k/v bf16 hi/lo head layout
    {
        QkvArgs a;
        a.A = lof;
        a.Bh[0] = wqh; a.Bl[0] = wql; a.bias[0] = qb; a.gain[0] = qg; a.beta[0] = qbe;
        a.Bh[1] = wkh; a.Bl[1] = wkl; a.bias[1] = kb; a.gain[1] = kg; a.beta[1] = kbe;
        a.Bh[2] = wvh; a.Bl[2] = wvl; a.bias[2] = vb; a.gain[2] = vg; a.beta[2] = vbe;
        a.Oh[0] = (bf16*)symaddr(g_qph); a.Ol[0] = (bf16*)symaddr(g_qpl);
        a.Oh[1] = (bf16*)symaddr(g_kph); a.Ol[1] = (bf16*)symaddr(g_kpl);
        a.Oh[2] = (bf16*)symaddr(g_vph); a.Ol[2] = (bf16*)symaddr(g_vpl);
        gemm_qkv<<<dim3(DD/64, BSR/128, 3), 256, QKV_SMEM>>>(a);
    }

    attn_mma<<<dim3(SS/64, BB*HH), 128, AT_SMEM>>>();

    // attn out projection (fp16 A = ctx)
    {
        GArgs a = {};
        a.A = cxf; a.Bh = woh; a.Bl = wol;
        a.C = proj; a.N = DD; a.K = DD;
        gemm_mma<0><<<dim3(DD/128, BSR/128), 256, GEMM_SMEM>>>(a);
    }
    ln_residual_kernel<1><<<BSR, 256>>>(x, proj, ob, ang, anb, out1, o1f);

    // FFN1 with fused bias+gelu -> fp16 plane
    {
        GArgs a = {};
        a.A = o1f; a.Bh = w1h; a.Bl = w1l;
        a.bias = b1; a.Cf = f1f; a.N = MLPD; a.K = DD;
        gemm_mma<1><<<dim3(MLPD/128, BSR/128), 256, GEMM_SMEM>>>(a);
    }
    // FFN2
    {
        GArgs a = {};
        a.A = f1f; a.Bh = w2h; a.Bl = w2l;
        a.C = ffn2; a.N = DD; a.K = MLPD;
        gemm_mma<0><<<dim3(DD/128, BSR/128), 256, GEMM_SMEM>>>(a);
    }
    ln_residual_kernel<0><<<BSR, 256>>>(out1, ffn2, b2, fng, fnb, out, nullptr);
}